// round 5
// baseline (speedup 1.0000x reference)
#include <cuda_runtime.h>
#include <math.h>
#include <float.h>

// Problem constants
#define NN   50000
#define EE   400000
#define INCH 128
#define CCH  32
#define HH1  8
#define HIDD 256
#define TDD  64
#define EDD  128

// ---------------- scratch (device globals; referenced directly in device code)
__device__ __align__(16) float g_edge_attr[(size_t)EE * EDD];     // 205 MB
__device__ __align__(16) float g_q1[(size_t)NN * HIDD];
__device__ __align__(16) float g_k1[(size_t)NN * HIDD];
__device__ __align__(16) float g_v1[(size_t)NN * HIDD];
__device__ __align__(16) float g_s1[(size_t)NN * HIDD];
__device__ __align__(16) float g_e1[(size_t)EE * HIDD];           // 410 MB
__device__ __align__(16) float g_logit1[(size_t)EE * HH1];
__device__ __align__(16) float g_m1[(size_t)NN * HH1];
__device__ __align__(16) float g_sum1[(size_t)NN * HH1];
__device__ __align__(16) float g_agg1[(size_t)NN * HIDD];
__device__ __align__(16) float g_h[(size_t)NN * HIDD];
__device__ __align__(16) float g_q2[(size_t)NN * CCH];
__device__ __align__(16) float g_k2[(size_t)NN * CCH];
__device__ __align__(16) float g_v2[(size_t)NN * CCH];
__device__ __align__(16) float g_s2[(size_t)NN * CCH];
__device__ __align__(16) float g_e2[(size_t)EE * CCH];
__device__ __align__(16) float g_logit2[(size_t)EE];
__device__ __align__(16) float g_m2[(size_t)NN];
__device__ __align__(16) float g_sum2[(size_t)NN];
__device__ __align__(16) float g_agg2[(size_t)NN * CCH];

// canonical int32 indices (dtype-agnostic ingestion)
__device__ int g_src[EE];
__device__ int g_dst[EE];
__device__ int g_is64;

// ---------------- index ingestion ---------------------------------------------
// Detect whether edge_index is int64 or int32.
// If int64 (ids < 2^31): every odd 32-bit word is 0.
// If int32: odd words are random node ids; all-zero probability ~0.
__global__ void k_detect(const int* __restrict__ words) {
    __shared__ int nz;
    if (threadIdx.x == 0) nz = 0;
    __syncthreads();
    for (int i = threadIdx.x; i < 1024; i += blockDim.x)
        if (words[2 * i + 1] != 0) atomicAdd(&nz, 1);
    __syncthreads();
    if (threadIdx.x == 0) g_is64 = (nz == 0) ? 1 : 0;
}

__global__ void k_convert(const void* __restrict__ ei) {
    int i = blockIdx.x * blockDim.x + threadIdx.x;
    if (i >= EE) return;
    int s, d;
    if (g_is64) {
        const long long* p = (const long long*)ei;
        s = (int)p[i];
        d = (int)p[EE + i];
    } else {
        const int* p = (const int*)ei;
        s = p[i];
        d = p[EE + i];
    }
    // clamp defensively (guaranteed in-range if detection correct)
    s = min(max(s, 0), NN - 1);
    d = min(max(d, 0), NN - 1);
    g_src[i] = s;
    g_dst[i] = d;
}

// ---------------- init kernels ------------------------------------------------
__global__ void k_init() {
    int i = blockIdx.x * blockDim.x + threadIdx.x;
    if (i < NN * HIDD) g_agg1[i] = 0.f;
    if (i < NN * HH1) { g_m1[i] = -FLT_MAX; g_sum1[i] = 0.f; }
    if (i < NN * CCH)  g_agg2[i] = 0.f;
    if (i < NN)       { g_m2[i] = -FLT_MAX; g_sum2[i] = 0.f; }
}

// ---------------- edge features ----------------------------------------------
// edge_attr[e, 0:64]  = cos((last_update[src]-t) * tw + tb)
// edge_attr[e, 64:128]= msg
__global__ void k_edge_attr(const float* __restrict__ last_update,
                            const float* __restrict__ t,
                            const float* __restrict__ msg,
                            const float* __restrict__ tw,
                            const float* __restrict__ tb) {
    int i = blockIdx.x * blockDim.x + threadIdx.x;
    if (i >= EE * EDD) return;
    int e = i >> 7;
    int c = i & 127;
    float v;
    if (c < TDD) {
        float rt = last_update[g_src[e]] - t[e];
        v = cosf(rt * tw[c] + tb[c]);
    } else {
        v = msg[e * 64 + (c - 64)];
    }
    g_edge_attr[i] = v;
}

// ---------------- fp32 tiled GEMM body: C = A[MxK] * W[KxN] (+bias) ----------
template <int BM, int BN, int BK, int TM, int TN>
__device__ __forceinline__ void gemm_body(const float* __restrict__ A,
                                          const float* __restrict__ W,
                                          const float* __restrict__ bias,
                                          float* __restrict__ C,
                                          int M, int K, int Nc) {
    __shared__ float As[BK][BM + 1];
    __shared__ float Bs[BK][BN];
    constexpr int THREADS = (BM / TM) * (BN / TN);
    const int tid = threadIdx.x;
    const int tx = tid % (BN / TN);
    const int ty = tid / (BN / TN);
    const int m0 = blockIdx.y * BM;
    const int n0 = blockIdx.x * BN;

    float acc[TM][TN];
#pragma unroll
    for (int i = 0; i < TM; i++)
#pragma unroll
        for (int j = 0; j < TN; j++) acc[i][j] = 0.f;

    for (int k0 = 0; k0 < K; k0 += BK) {
#pragma unroll 4
        for (int i = tid; i < BM * BK; i += THREADS) {
            int r = i / BK, c = i % BK;
            int gm = m0 + r;
            As[c][r] = (gm < M) ? A[(long long)gm * K + k0 + c] : 0.f;
        }
#pragma unroll 4
        for (int i = tid; i < BK * BN; i += THREADS) {
            int r = i / BN, c = i % BN;
            int gn = n0 + c;
            Bs[r][c] = (gn < Nc) ? W[(long long)(k0 + r) * Nc + gn] : 0.f;
        }
        __syncthreads();
#pragma unroll
        for (int kk = 0; kk < BK; kk++) {
            float ra[TM], rb[TN];
#pragma unroll
            for (int i = 0; i < TM; i++) ra[i] = As[kk][ty * TM + i];
#pragma unroll
            for (int j = 0; j < TN; j++) rb[j] = Bs[kk][tx * TN + j];
#pragma unroll
            for (int i = 0; i < TM; i++)
#pragma unroll
                for (int j = 0; j < TN; j++) acc[i][j] += ra[i] * rb[j];
        }
        __syncthreads();
    }

#pragma unroll
    for (int i = 0; i < TM; i++) {
        int gm = m0 + ty * TM + i;
        if (gm >= M) continue;
#pragma unroll
        for (int j = 0; j < TN; j++) {
            int gn = n0 + tx * TN + j;
            if (gn >= Nc) continue;
            float v = acc[i][j];
            if (bias) v += bias[gn];
            C[(long long)gm * Nc + gn] = v;
        }
    }
}

// GEMM wrappers (scratch referenced from device code — no symbol lookup)
__global__ void k_gemm_q1(const float* __restrict__ x, const float* __restrict__ W, const float* __restrict__ b) {
    gemm_body<128, 64, 16, 8, 4>(x, W, b, g_q1, NN, INCH, HIDD);
}
__global__ void k_gemm_k1(const float* __restrict__ x, const float* __restrict__ W, const float* __restrict__ b) {
    gemm_body<128, 64, 16, 8, 4>(x, W, b, g_k1, NN, INCH, HIDD);
}
__global__ void k_gemm_v1(const float* __restrict__ x, const float* __restrict__ W, const float* __restrict__ b) {
    gemm_body<128, 64, 16, 8, 4>(x, W, b, g_v1, NN, INCH, HIDD);
}
__global__ void k_gemm_s1(const float* __restrict__ x, const float* __restrict__ W, const float* __restrict__ b) {
    gemm_body<128, 64, 16, 8, 4>(x, W, b, g_s1, NN, INCH, HIDD);
}
__global__ void k_gemm_e1(const float* __restrict__ W) {
    gemm_body<128, 64, 16, 8, 4>(g_edge_attr, W, nullptr, g_e1, EE, EDD, HIDD);
}
__global__ void k_gemm_q2(const float* __restrict__ W, const float* __restrict__ b) {
    gemm_body<64, 32, 16, 4, 2>(g_h, W, b, g_q2, NN, HIDD, CCH);
}
__global__ void k_gemm_k2(const float* __restrict__ W, const float* __restrict__ b) {
    gemm_body<64, 32, 16, 4, 2>(g_h, W, b, g_k2, NN, HIDD, CCH);
}
__global__ void k_gemm_v2(const float* __restrict__ W, const float* __restrict__ b) {
    gemm_body<64, 32, 16, 4, 2>(g_h, W, b, g_v2, NN, HIDD, CCH);
}
__global__ void k_gemm_s2(const float* __restrict__ W, const float* __restrict__ b) {
    gemm_body<64, 32, 16, 4, 2>(g_h, W, b, g_s2, NN, HIDD, CCH);
}
__global__ void k_gemm_e2(const float* __restrict__ W) {
    gemm_body<64, 32, 16, 4, 2>(g_edge_attr, W, nullptr, g_e2, EE, EDD, CCH);
}

// ---------------- attention ---------------------------------------------------
__device__ __forceinline__ void atomicMaxFloat(float* addr, float value) {
    if (value >= 0.f)
        atomicMax((int*)addr, __float_as_int(value));
    else
        atomicMin((unsigned int*)addr, __float_as_uint(value));
}

// warp per (edge, head); C == 32
template <int H, int C>
__device__ __forceinline__ void logits_body(const float* __restrict__ q,
                                            const float* __restrict__ k,
                                            const float* __restrict__ ev,
                                            float* __restrict__ logit,
                                            float* __restrict__ mbuf) {
    int w = (blockIdx.x * blockDim.x + threadIdx.x) >> 5;
    int lane = threadIdx.x & 31;
    if (w >= EE * H) return;
    int e = w / H;
    int h = w - e * H;
    int s = g_src[e];
    int d = g_dst[e];
    float qa = q[(long long)d * (H * C) + h * C + lane];
    float kv = k[(long long)s * (H * C) + h * C + lane] +
               ev[(long long)e * (H * C) + h * C + lane];
    float p = qa * kv;
#pragma unroll
    for (int o = 16; o > 0; o >>= 1) p += __shfl_xor_sync(0xffffffffu, p, o);
    if (lane == 0) {
        float lg = p * 0.17677669529663687f;  // 1/sqrt(32)
        logit[(long long)e * H + h] = lg;
        atomicMaxFloat(&mbuf[d * H + h], lg);
    }
}
__global__ void k_logits1() {
    logits_body<HH1, CCH>(g_q1, g_k1, g_e1, g_logit1, g_m1);
}
__global__ void k_logits2() {
    logits_body<1, CCH>(g_q2, g_k2, g_e2, g_logit2, g_m2);
}

template <int H>
__device__ __forceinline__ void softmax_exp_body(float* __restrict__ logit,
                                                 const float* __restrict__ mbuf,
                                                 float* __restrict__ sbuf) {
    int i = blockIdx.x * blockDim.x + threadIdx.x;
    if (i >= EE * H) return;
    int e = i / H;
    int h = i - e * H;
    int d = g_dst[e];
    float v = expf(logit[i] - mbuf[d * H + h]);
    logit[i] = v;  // in place: now holds exp(logit - m)
    atomicAdd(&sbuf[d * H + h], v);
}
__global__ void k_softmax1() { softmax_exp_body<HH1>(g_logit1, g_m1, g_sum1); }
__global__ void k_softmax2() { softmax_exp_body<1>(g_logit2, g_m2, g_sum2); }

// thread per (edge, head, channel)
template <int H, int C>
__device__ __forceinline__ void agg_body(const float* __restrict__ ealpha,
                                         const float* __restrict__ sbuf,
                                         const float* __restrict__ v,
                                         const float* __restrict__ ev,
                                         float* __restrict__ agg) {
    long long i = (long long)blockIdx.x * blockDim.x + threadIdx.x;
    if (i >= (long long)EE * H * C) return;
    int e = (int)(i / (H * C));
    int r = (int)(i - (long long)e * (H * C));  // h*C + c
    int h = r / C;
    int s = g_src[e];
    int d = g_dst[e];
    float a = ealpha[(long long)e * H + h] / (sbuf[d * H + h] + 1e-16f);
    float val = a * (v[(long long)s * (H * C) + r] + ev[(long long)e * (H * C) + r]);
    atomicAdd(&agg[(long long)d * (H * C) + r], val);
}
__global__ void k_agg1() { agg_body<HH1, CCH>(g_logit1, g_sum1, g_v1, g_e1, g_agg1); }
__global__ void k_agg2() { agg_body<1, CCH>(g_logit2, g_sum2, g_v2, g_e2, g_agg2); }

// h = relu(agg1 + s1)
__global__ void k_hidden() {
    int i = blockIdx.x * blockDim.x + threadIdx.x;
    if (i < NN * HIDD) g_h[i] = fmaxf(g_agg1[i] + g_s1[i], 0.f);
}
// out = relu(agg2 + s2)
__global__ void k_output(float* __restrict__ out) {
    int i = blockIdx.x * blockDim.x + threadIdx.x;
    if (i < NN * CCH) out[i] = fmaxf(g_agg2[i] + g_s2[i], 0.f);
}

// ---------------- launch ------------------------------------------------------
extern "C" void kernel_launch(void* const* d_in, const int* in_sizes, int n_in,
                              void* d_out, int out_size) {
    const float* x           = (const float*)d_in[0];
    const float* last_update = (const float*)d_in[1];
    const void*  ei          = d_in[2];
    const float* t           = (const float*)d_in[3];
    const float* msg         = (const float*)d_in[4];
    const float* tw          = (const float*)d_in[5];
    const float* tb          = (const float*)d_in[6];
    const float* Wq1 = (const float*)d_in[7],  *bq1 = (const float*)d_in[8];
    const float* Wk1 = (const float*)d_in[9],  *bk1 = (const float*)d_in[10];
    const float* Wv1 = (const float*)d_in[11], *bv1 = (const float*)d_in[12];
    const float* We1 = (const float*)d_in[13];
    const float* Ws1 = (const float*)d_in[14], *bs1 = (const float*)d_in[15];
    const float* Wq2 = (const float*)d_in[16], *bq2 = (const float*)d_in[17];
    const float* Wk2 = (const float*)d_in[18], *bk2 = (const float*)d_in[19];
    const float* Wv2 = (const float*)d_in[20], *bv2 = (const float*)d_in[21];
    const float* We2 = (const float*)d_in[22];
    const float* Ws2 = (const float*)d_in[23], *bs2 = (const float*)d_in[24];

    float* out = (float*)d_out;

    // index ingestion (dtype-agnostic)
    k_detect<<<1, 256>>>((const int*)ei);
    k_convert<<<(EE + 255) / 256, 256>>>(ei);

    // init accumulators
    k_init<<<(NN * HIDD + 255) / 256, 256>>>();

    // edge features
    k_edge_attr<<<(EE * EDD + 255) / 256, 256>>>(last_update, t, msg, tw, tb);

    // layer-1 node GEMMs: (N,128) @ (128,256)
    {
        dim3 grid(HIDD / 64, (NN + 127) / 128);
        k_gemm_q1<<<grid, 256>>>(x, Wq1, bq1);
        k_gemm_k1<<<grid, 256>>>(x, Wk1, bk1);
        k_gemm_v1<<<grid, 256>>>(x, Wv1, bv1);
        k_gemm_s1<<<grid, 256>>>(x, Ws1, bs1);
    }
    // layer-1 edge GEMM: (E,128) @ (128,256)
    {
        dim3 grid(HIDD / 64, (EE + 127) / 128);
        k_gemm_e1<<<grid, 256>>>(We1);
    }

    // layer-1 attention
    k_logits1<<<(EE * HH1 + 7) / 8, 256>>>();
    k_softmax1<<<(EE * HH1 + 255) / 256, 256>>>();
    k_agg1<<<(int)(((long long)EE * HH1 * CCH + 255) / 256), 256>>>();
    k_hidden<<<(NN * HIDD + 255) / 256, 256>>>();

    // layer-2 node GEMMs: (N,256) @ (256,32)
    {
        dim3 grid(CCH / 32, (NN + 63) / 64);
        k_gemm_q2<<<grid, 256>>>(Wq2, bq2);
        k_gemm_k2<<<grid, 256>>>(Wk2, bk2);
        k_gemm_v2<<<grid, 256>>>(Wv2, bv2);
        k_gemm_s2<<<grid, 256>>>(Ws2, bs2);
    }
    // layer-2 edge GEMM: (E,128) @ (128,32)
    {
        dim3 grid(CCH / 32, (EE + 63) / 64);
        k_gemm_e2<<<grid, 256>>>(We2);
    }

    // layer-2 attention (H=1)
    k_logits2<<<(EE + 7) / 8, 256>>>();
    k_softmax2<<<(EE + 255) / 256, 256>>>();
    k_agg2<<<(int)(((long long)EE * CCH + 255) / 256), 256>>>();

    // final: relu(agg2 + skip2)
    k_output<<<(NN * CCH + 255) / 256, 256>>>(out);
}

// round 6
// speedup vs baseline: 1.3658x; 1.3658x over previous
#include <cuda_runtime.h>
#include <math.h>
#include <float.h>

// Problem constants
#define NN   50000
#define EE   400000
#define INCH 128
#define CCH  32
#define HH1  8
#define HIDD 256
#define TDD  64
#define EDD  128

// ---------------- scratch (device globals; referenced directly in device code)
__device__ __align__(16) float g_edge_attr[(size_t)EE * EDD];     // 205 MB
__device__ __align__(16) float g_q1[(size_t)NN * HIDD];
__device__ __align__(16) float g_k1[(size_t)NN * HIDD];
__device__ __align__(16) float g_v1[(size_t)NN * HIDD];
__device__ __align__(16) float g_s1[(size_t)NN * HIDD];
__device__ __align__(16) float g_e1[(size_t)EE * HIDD];           // 410 MB
__device__ __align__(16) float g_h[(size_t)NN * HIDD];
__device__ __align__(16) float g_q2[(size_t)NN * CCH];
__device__ __align__(16) float g_k2[(size_t)NN * CCH];
__device__ __align__(16) float g_v2[(size_t)NN * CCH];
__device__ __align__(16) float g_s2[(size_t)NN * CCH];
__device__ __align__(16) float g_e2[(size_t)EE * CCH];

// indices + CSR
__device__ int g_src[EE];
__device__ int g_dst[EE];
__device__ int g_is64;
__device__ int g_deg[NN];
__device__ int g_off[NN + 1];
__device__ int g_cur[NN];
__device__ int g_eidx[EE];

// ---------------- index ingestion ---------------------------------------------
// int64 vs int32 detection: if int64 (ids < 2^31) every odd 32-bit word is 0.
__global__ void k_detect(const int* __restrict__ words) {
    __shared__ int nz;
    if (threadIdx.x == 0) nz = 0;
    __syncthreads();
    for (int i = threadIdx.x; i < 1024; i += blockDim.x)
        if (words[2 * i + 1] != 0) atomicAdd(&nz, 1);
    __syncthreads();
    if (threadIdx.x == 0) g_is64 = (nz == 0) ? 1 : 0;
}

__global__ void k_convert(const void* __restrict__ ei) {
    int i = blockIdx.x * blockDim.x + threadIdx.x;
    if (i >= EE) return;
    int s, d;
    if (g_is64) {
        const long long* p = (const long long*)ei;
        s = (int)p[i];
        d = (int)p[EE + i];
    } else {
        const int* p = (const int*)ei;
        s = p[i];
        d = p[EE + i];
    }
    s = min(max(s, 0), NN - 1);
    d = min(max(d, 0), NN - 1);
    g_src[i] = s;
    g_dst[i] = d;
}

// ---------------- CSR build ---------------------------------------------------
__global__ void k_zero_deg() {
    int i = blockIdx.x * blockDim.x + threadIdx.x;
    if (i < NN) g_deg[i] = 0;
}
__global__ void k_count() {
    int e = blockIdx.x * blockDim.x + threadIdx.x;
    if (e < EE) atomicAdd(&g_deg[g_dst[e]], 1);
}
// single-block exclusive scan over g_deg -> g_off, g_cur
__global__ void k_scan() {
    __shared__ int carry;
    __shared__ int wsum[32];
    if (threadIdx.x == 0) carry = 0;
    __syncthreads();
    int lane = threadIdx.x & 31, wid = threadIdx.x >> 5;
    for (int base = 0; base < NN; base += 1024) {
        int i = base + threadIdx.x;
        int v = (i < NN) ? g_deg[i] : 0;
        int x = v;
#pragma unroll
        for (int o = 1; o < 32; o <<= 1) {
            int y = __shfl_up_sync(0xffffffffu, x, o);
            if (lane >= o) x += y;
        }
        if (lane == 31) wsum[wid] = x;
        __syncthreads();
        if (wid == 0) {
            int s = wsum[lane];
#pragma unroll
            for (int o = 1; o < 32; o <<= 1) {
                int y = __shfl_up_sync(0xffffffffu, s, o);
                if (lane >= o) s += y;
            }
            wsum[lane] = s;
        }
        __syncthreads();
        int incl = x + (wid > 0 ? wsum[wid - 1] : 0) + carry;
        if (i < NN) {
            g_off[i + 1] = incl;
            g_cur[i] = incl - v;
        }
        __syncthreads();
        if (threadIdx.x == 1023) carry = incl;
        __syncthreads();
    }
    if (threadIdx.x == 0) g_off[0] = 0;
}
__global__ void k_fill() {
    int e = blockIdx.x * blockDim.x + threadIdx.x;
    if (e < EE) {
        int p = atomicAdd(&g_cur[g_dst[e]], 1);
        g_eidx[p] = e;
    }
}

// ---------------- edge features (float4) --------------------------------------
__global__ void k_edge_attr(const float* __restrict__ lu, const float* __restrict__ t,
                            const float* __restrict__ msg,
                            const float* __restrict__ tw, const float* __restrict__ tb) {
    int i = blockIdx.x * blockDim.x + threadIdx.x;
    if (i >= EE * 32) return;
    int e = i >> 5;
    int c = (i & 31) << 2;
    float4 r;
    if (c < TDD) {
        float rt = lu[g_src[e]] - t[e];
        r.x = cosf(rt * tw[c + 0] + tb[c + 0]);
        r.y = cosf(rt * tw[c + 1] + tb[c + 1]);
        r.z = cosf(rt * tw[c + 2] + tb[c + 2]);
        r.w = cosf(rt * tw[c + 3] + tb[c + 3]);
    } else {
        r = *(const float4*)(msg + e * 64 + (c - 64));
    }
    *(float4*)(g_edge_attr + (long long)e * EDD + c) = r;
}

// ---------------- fast SGEMM: 128x128 tile, BK=16, 8x8 per thread -------------
__device__ __forceinline__ void sgemm128_body(const float* __restrict__ A,
                                              const float* __restrict__ W,
                                              const float* __restrict__ bias,
                                              float* __restrict__ C,
                                              int M, int K, int N) {
    __shared__ float As[16][128];
    __shared__ float Bs[16][128];
    const int tid = threadIdx.x;
    const int m0 = blockIdx.y * 128, n0 = blockIdx.x * 128;
    const int tx = tid % 16, ty = tid / 16;

    float acc[8][8];
#pragma unroll
    for (int i = 0; i < 8; i++)
#pragma unroll
        for (int j = 0; j < 8; j++) acc[i][j] = 0.f;

    for (int k0 = 0; k0 < K; k0 += 16) {
#pragma unroll
        for (int it = 0; it < 2; it++) {
            int id = tid + it * 256;
            int r = id >> 2, c = (id & 3) << 2;  // r:0..127, c:0,4,8,12
            int gm = m0 + r;
            float4 a = (gm < M) ? *(const float4*)(A + (long long)gm * K + k0 + c)
                                : make_float4(0.f, 0.f, 0.f, 0.f);
            As[c + 0][r] = a.x;
            As[c + 1][r] = a.y;
            As[c + 2][r] = a.z;
            As[c + 3][r] = a.w;
        }
#pragma unroll
        for (int it = 0; it < 2; it++) {
            int id = tid + it * 256;
            int r = id >> 5, c = (id & 31) << 2;  // r:0..15, c:0..124
            int gn = n0 + c;
            float4 b = (gn < N) ? *(const float4*)(W + (long long)(k0 + r) * N + gn)
                                : make_float4(0.f, 0.f, 0.f, 0.f);
            *(float4*)&Bs[r][c] = b;
        }
        __syncthreads();
#pragma unroll
        for (int kk = 0; kk < 16; kk++) {
            float4 a0 = *(float4*)&As[kk][ty * 8];
            float4 a1 = *(float4*)&As[kk][ty * 8 + 4];
            float4 b0 = *(float4*)&Bs[kk][tx * 8];
            float4 b1 = *(float4*)&Bs[kk][tx * 8 + 4];
            float ra[8] = {a0.x, a0.y, a0.z, a0.w, a1.x, a1.y, a1.z, a1.w};
            float rb[8] = {b0.x, b0.y, b0.z, b0.w, b1.x, b1.y, b1.z, b1.w};
#pragma unroll
            for (int i = 0; i < 8; i++)
#pragma unroll
                for (int j = 0; j < 8; j++) acc[i][j] += ra[i] * rb[j];
        }
        __syncthreads();
    }

#pragma unroll
    for (int i = 0; i < 8; i++) {
        int gm = m0 + ty * 8 + i;
        if (gm >= M) continue;
#pragma unroll
        for (int j = 0; j < 8; j++) {
            int gn = n0 + tx * 8 + j;
            if (gn >= N) continue;
            float v = acc[i][j];
            if (bias) v += bias[gn];
            C[(long long)gm * N + gn] = v;
        }
    }
}

__global__ void k_g_q1(const float* __restrict__ x, const float* __restrict__ W, const float* __restrict__ b) {
    sgemm128_body(x, W, b, g_q1, NN, INCH, HIDD);
}
__global__ void k_g_k1(const float* __restrict__ x, const float* __restrict__ W, const float* __restrict__ b) {
    sgemm128_body(x, W, b, g_k1, NN, INCH, HIDD);
}
__global__ void k_g_v1(const float* __restrict__ x, const float* __restrict__ W, const float* __restrict__ b) {
    sgemm128_body(x, W, b, g_v1, NN, INCH, HIDD);
}
__global__ void k_g_s1(const float* __restrict__ x, const float* __restrict__ W, const float* __restrict__ b) {
    sgemm128_body(x, W, b, g_s1, NN, INCH, HIDD);
}
__global__ void k_g_e1(const float* __restrict__ W) {
    sgemm128_body(g_edge_attr, W, nullptr, g_e1, EE, EDD, HIDD);
}

// ---------------- small-N SGEMM (layer 2): 64x32 tile --------------------------
template <int BM, int BN, int BK, int TM, int TN>
__device__ __forceinline__ void gemm_body(const float* __restrict__ A,
                                          const float* __restrict__ W,
                                          const float* __restrict__ bias,
                                          float* __restrict__ C,
                                          int M, int K, int N) {
    __shared__ float As[BK][BM + 1];
    __shared__ float Bs[BK][BN];
    constexpr int THREADS = (BM / TM) * (BN / TN);
    const int tid = threadIdx.x;
    const int tx = tid % (BN / TN);
    const int ty = tid / (BN / TN);
    const int m0 = blockIdx.y * BM;
    const int n0 = blockIdx.x * BN;

    float acc[TM][TN];
#pragma unroll
    for (int i = 0; i < TM; i++)
#pragma unroll
        for (int j = 0; j < TN; j++) acc[i][j] = 0.f;

    for (int k0 = 0; k0 < K; k0 += BK) {
#pragma unroll 4
        for (int i = tid; i < BM * BK; i += THREADS) {
            int r = i / BK, c = i % BK;
            int gm = m0 + r;
            As[c][r] = (gm < M) ? A[(long long)gm * K + k0 + c] : 0.f;
        }
#pragma unroll 4
        for (int i = tid; i < BK * BN; i += THREADS) {
            int r = i / BN, c = i % BN;
            int gn = n0 + c;
            Bs[r][c] = (gn < N) ? W[(long long)(k0 + r) * N + gn] : 0.f;
        }
        __syncthreads();
#pragma unroll
        for (int kk = 0; kk < BK; kk++) {
            float ra[TM], rb[TN];
#pragma unroll
            for (int i = 0; i < TM; i++) ra[i] = As[kk][ty * TM + i];
#pragma unroll
            for (int j = 0; j < TN; j++) rb[j] = Bs[kk][tx * TN + j];
#pragma unroll
            for (int i = 0; i < TM; i++)
#pragma unroll
                for (int j = 0; j < TN; j++) acc[i][j] += ra[i] * rb[j];
        }
        __syncthreads();
    }

#pragma unroll
    for (int i = 0; i < TM; i++) {
        int gm = m0 + ty * TM + i;
        if (gm >= M) continue;
#pragma unroll
        for (int j = 0; j < TN; j++) {
            int gn = n0 + tx * TN + j;
            if (gn >= N) continue;
            float v = acc[i][j];
            if (bias) v += bias[gn];
            C[(long long)gm * N + gn] = v;
        }
    }
}
__global__ void k_g_q2(const float* __restrict__ W, const float* __restrict__ b) {
    gemm_body<64, 32, 16, 4, 2>(g_h, W, b, g_q2, NN, HIDD, CCH);
}
__global__ void k_g_k2(const float* __restrict__ W, const float* __restrict__ b) {
    gemm_body<64, 32, 16, 4, 2>(g_h, W, b, g_k2, NN, HIDD, CCH);
}
__global__ void k_g_v2(const float* __restrict__ W, const float* __restrict__ b) {
    gemm_body<64, 32, 16, 4, 2>(g_h, W, b, g_v2, NN, HIDD, CCH);
}
__global__ void k_g_s2(const float* __restrict__ W, const float* __restrict__ b) {
    gemm_body<64, 32, 16, 4, 2>(g_h, W, b, g_s2, NN, HIDD, CCH);
}
__global__ void k_g_e2(const float* __restrict__ W) {
    gemm_body<64, 32, 16, 4, 2>(g_edge_attr, W, nullptr, g_e2, EE, EDD, CCH);
}

// ---------------- fused attention (CSR, online softmax, + skip + relu) --------
// one warp per (dst, head); lane = channel (C == 32)
template <int H, int C>
__device__ __forceinline__ void attn_body(const float* __restrict__ q,
                                          const float* __restrict__ k,
                                          const float* __restrict__ v,
                                          const float* __restrict__ ev,
                                          const float* __restrict__ skip,
                                          float* __restrict__ outp) {
    int w = (blockIdx.x * blockDim.x + threadIdx.x) >> 5;
    int lane = threadIdx.x & 31;
    if (w >= NN * H) return;
    int d = w / H;
    int h = w - d * H;

    float qc = q[(d * H + h) * C + lane];
    int beg = g_off[d], end = g_off[d + 1];

    float m = -FLT_MAX, ssum = 0.f, acc = 0.f;
    for (int i = beg; i < end; i++) {
        int e = g_eidx[i];
        int s = g_src[e];
        int ebase = (e * H + h) * C + lane;
        int sbase = (s * H + h) * C + lane;
        float ec = ev[ebase];
        float kc = k[sbase] + ec;
        float p = qc * kc;
#pragma unroll
        for (int o = 16; o; o >>= 1) p += __shfl_xor_sync(0xffffffffu, p, o);
        float lg = p * 0.17677669529663687f;  // 1/sqrt(32)
        if (lg > m) {
            float f = expf(m - lg);  // m == -FLT_MAX -> 0
            ssum *= f;
            acc *= f;
            m = lg;
        }
        float wt = expf(lg - m);
        ssum += wt;
        acc += wt * (v[sbase] + ec);
    }
    float val = acc / (ssum + 1e-16f);
    int oi = (d * H + h) * C + lane;
    outp[oi] = fmaxf(val + skip[oi], 0.f);
}
__global__ void k_attn1() { attn_body<HH1, CCH>(g_q1, g_k1, g_v1, g_e1, g_s1, g_h); }
__global__ void k_attn2(float* __restrict__ out) {
    attn_body<1, CCH>(g_q2, g_k2, g_v2, g_e2, g_s2, out);
}

// ---------------- launch ------------------------------------------------------
extern "C" void kernel_launch(void* const* d_in, const int* in_sizes, int n_in,
                              void* d_out, int out_size) {
    const float* x           = (const float*)d_in[0];
    const float* last_update = (const float*)d_in[1];
    const void*  ei          = d_in[2];
    const float* t           = (const float*)d_in[3];
    const float* msg         = (const float*)d_in[4];
    const float* tw          = (const float*)d_in[5];
    const float* tb          = (const float*)d_in[6];
    const float* Wq1 = (const float*)d_in[7],  *bq1 = (const float*)d_in[8];
    const float* Wk1 = (const float*)d_in[9],  *bk1 = (const float*)d_in[10];
    const float* Wv1 = (const float*)d_in[11], *bv1 = (const float*)d_in[12];
    const float* We1 = (const float*)d_in[13];
    const float* Ws1 = (const float*)d_in[14], *bs1 = (const float*)d_in[15];
    const float* Wq2 = (const float*)d_in[16], *bq2 = (const float*)d_in[17];
    const float* Wk2 = (const float*)d_in[18], *bk2 = (const float*)d_in[19];
    const float* Wv2 = (const float*)d_in[20], *bv2 = (const float*)d_in[21];
    const float* We2 = (const float*)d_in[22];
    const float* Ws2 = (const float*)d_in[23], *bs2 = (const float*)d_in[24];

    float* out = (float*)d_out;

    // index ingestion + CSR
    k_detect<<<1, 256>>>((const int*)ei);
    k_convert<<<(EE + 255) / 256, 256>>>(ei);
    k_zero_deg<<<(NN + 255) / 256, 256>>>();
    k_count<<<(EE + 255) / 256, 256>>>();
    k_scan<<<1, 1024>>>();
    k_fill<<<(EE + 255) / 256, 256>>>();

    // edge features
    k_edge_attr<<<(EE * 32 + 255) / 256, 256>>>(last_update, t, msg, tw, tb);

    // layer-1 GEMMs (128x128 tiles)
    {
        dim3 gn(HIDD / 128, (NN + 127) / 128);
        k_g_q1<<<gn, 256>>>(x, Wq1, bq1);
        k_g_k1<<<gn, 256>>>(x, Wk1, bk1);
        k_g_v1<<<gn, 256>>>(x, Wv1, bv1);
        k_g_s1<<<gn, 256>>>(x, Ws1, bs1);
        dim3 ge(HIDD / 128, EE / 128);
        k_g_e1<<<ge, 256>>>(We1);
    }

    // layer-1 fused attention -> g_h (with skip + relu)
    k_attn1<<<(NN * HH1 * 32 + 255) / 256, 256>>>();

    // layer-2 GEMMs
    {
        dim3 gn(1, (NN + 63) / 64);
        k_g_q2<<<gn, 256>>>(Wq2, bq2);
        k_g_k2<<<gn, 256>>>(Wk2, bk2);
        k_g_v2<<<gn, 256>>>(Wv2, bv2);
        k_g_s2<<<gn, 256>>>(Ws2, bs2);
        dim3 ge(1, (EE + 63) / 64);
        k_g_e2<<<ge, 256>>>(We2);
    }

    // layer-2 fused attention -> out (with skip + relu)
    k_attn2<<<(NN * 32 + 255) / 256, 256>>>(out);
}

// round 7
// speedup vs baseline: 1.3890x; 1.0170x over previous
#include <cuda_runtime.h>
#include <math.h>
#include <float.h>

// Problem constants
#define NN   50000
#define EE   400000
#define INCH 128
#define CCH  32
#define HH1  8
#define HIDD 256
#define TDD  64
#define EDD  128

// ---------------- scratch (device globals; referenced directly in device code)
__device__ __align__(16) float g_edge_attr[(size_t)EE * EDD];     // 205 MB
__device__ __align__(16) float g_q1[(size_t)NN * HIDD];
__device__ __align__(16) float g_k1[(size_t)NN * HIDD];
__device__ __align__(16) float g_v1[(size_t)NN * HIDD];
__device__ __align__(16) float g_s1[(size_t)NN * HIDD];
__device__ __align__(16) float g_e1[(size_t)EE * HIDD];           // 410 MB
__device__ __align__(16) float g_h[(size_t)NN * HIDD];
__device__ __align__(16) float g_q2[(size_t)NN * CCH];
__device__ __align__(16) float g_k2[(size_t)NN * CCH];
__device__ __align__(16) float g_v2[(size_t)NN * CCH];
__device__ __align__(16) float g_s2[(size_t)NN * CCH];
__device__ __align__(16) float g_e2[(size_t)EE * CCH];

// indices + CSR
__device__ int g_src[EE];
__device__ int g_dst[EE];
__device__ int g_is64;
__device__ int g_deg[NN];
__device__ int g_off[NN + 1];
__device__ int g_cur[NN];
__device__ int g_eidx[EE];

// ---------------- index ingestion ---------------------------------------------
__global__ void k_detect(const int* __restrict__ words) {
    __shared__ int nz;
    if (threadIdx.x == 0) nz = 0;
    __syncthreads();
    for (int i = threadIdx.x; i < 1024; i += blockDim.x)
        if (words[2 * i + 1] != 0) atomicAdd(&nz, 1);
    __syncthreads();
    if (threadIdx.x == 0) g_is64 = (nz == 0) ? 1 : 0;
}

__global__ void k_convert(const void* __restrict__ ei) {
    int i = blockIdx.x * blockDim.x + threadIdx.x;
    if (i >= EE) return;
    int s, d;
    if (g_is64) {
        const long long* p = (const long long*)ei;
        s = (int)p[i];
        d = (int)p[EE + i];
    } else {
        const int* p = (const int*)ei;
        s = p[i];
        d = p[EE + i];
    }
    s = min(max(s, 0), NN - 1);
    d = min(max(d, 0), NN - 1);
    g_src[i] = s;
    g_dst[i] = d;
}

// ---------------- CSR build ---------------------------------------------------
__global__ void k_zero_deg() {
    int i = blockIdx.x * blockDim.x + threadIdx.x;
    if (i < NN) g_deg[i] = 0;
}
__global__ void k_count() {
    int e = blockIdx.x * blockDim.x + threadIdx.x;
    if (e < EE) atomicAdd(&g_deg[g_dst[e]], 1);
}
__global__ void k_scan() {
    __shared__ int carry;
    __shared__ int wsum[32];
    if (threadIdx.x == 0) carry = 0;
    __syncthreads();
    int lane = threadIdx.x & 31, wid = threadIdx.x >> 5;
    for (int base = 0; base < NN; base += 1024) {
        int i = base + threadIdx.x;
        int v = (i < NN) ? g_deg[i] : 0;
        int x = v;
#pragma unroll
        for (int o = 1; o < 32; o <<= 1) {
            int y = __shfl_up_sync(0xffffffffu, x, o);
            if (lane >= o) x += y;
        }
        if (lane == 31) wsum[wid] = x;
        __syncthreads();
        if (wid == 0) {
            int s = wsum[lane];
#pragma unroll
            for (int o = 1; o < 32; o <<= 1) {
                int y = __shfl_up_sync(0xffffffffu, s, o);
                if (lane >= o) s += y;
            }
            wsum[lane] = s;
        }
        __syncthreads();
        int incl = x + (wid > 0 ? wsum[wid - 1] : 0) + carry;
        if (i < NN) {
            g_off[i + 1] = incl;
            g_cur[i] = incl - v;
        }
        __syncthreads();
        if (threadIdx.x == 1023) carry = incl;
        __syncthreads();
    }
    if (threadIdx.x == 0) g_off[0] = 0;
}
__global__ void k_fill() {
    int e = blockIdx.x * blockDim.x + threadIdx.x;
    if (e < EE) {
        int p = atomicAdd(&g_cur[g_dst[e]], 1);
        g_eidx[p] = e;
    }
}

// ---------------- edge features (float4) --------------------------------------
__global__ void k_edge_attr(const float* __restrict__ lu, const float* __restrict__ t,
                            const float* __restrict__ msg,
                            const float* __restrict__ tw, const float* __restrict__ tb) {
    int i = blockIdx.x * blockDim.x + threadIdx.x;
    if (i >= EE * 32) return;
    int e = i >> 5;
    int c = (i & 31) << 2;
    float4 r;
    if (c < TDD) {
        float rt = lu[g_src[e]] - t[e];
        r.x = cosf(rt * tw[c + 0] + tb[c + 0]);
        r.y = cosf(rt * tw[c + 1] + tb[c + 1]);
        r.z = cosf(rt * tw[c + 2] + tb[c + 2]);
        r.w = cosf(rt * tw[c + 3] + tb[c + 3]);
    } else {
        r = *(const float4*)(msg + e * 64 + (c - 64));
    }
    *(float4*)(g_edge_attr + (long long)e * EDD + c) = r;
}

// ---------------- cp.async helpers --------------------------------------------
__device__ __forceinline__ void cpa16(void* s, const void* g) {
    unsigned sa = (unsigned)__cvta_generic_to_shared(s);
    asm volatile("cp.async.ca.shared.global [%0], [%1], 16;\n" ::"r"(sa), "l"(g));
}
__device__ __forceinline__ void cpa_commit() {
    asm volatile("cp.async.commit_group;\n" ::);
}
__device__ __forceinline__ void cpa_wait0() {
    asm volatile("cp.async.wait_group 0;\n" ::);
}

// ---------------- pipelined SGEMM: C = A[MxK] @ W[KxN] (+bias) ---------------
// 2-stage cp.async double buffer, BK=16.
template <int BM, int BN, int TM, int TN>
__device__ __forceinline__ void pgemm(const float* __restrict__ A,
                                      const float* __restrict__ W,
                                      const float* __restrict__ bias,
                                      float* __restrict__ C,
                                      int M, int K, int N) {
    constexpr int BK = 16;
    constexpr int TH = (BM / TM) * (BN / TN);
    __shared__ float As[2][BM * BK];  // row-major [r][k]
    __shared__ float Bs[2][BK * BN];  // row-major [k][n]
    const int tid = threadIdx.x;
    const int tx = tid % (BN / TN);
    const int ty = tid / (BN / TN);
    const int m0 = blockIdx.y * BM, n0 = blockIdx.x * BN;

    float acc[TM][TN];
#pragma unroll
    for (int i = 0; i < TM; i++)
#pragma unroll
        for (int j = 0; j < TN; j++) acc[i][j] = 0.f;

    constexpr int CA = BM * BK / 4;  // 16B chunks in A tile
    constexpr int CB = BK * BN / 4;  // 16B chunks in B tile
    const int nt = K / BK;

    // prefetch stage 0
    {
#pragma unroll
        for (int c = tid; c < CA; c += TH) {
            int r = c >> 2, kc = (c & 3) << 2;
            if (m0 + r < M) cpa16(&As[0][r * BK + kc], A + (size_t)(m0 + r) * K + kc);
        }
#pragma unroll
        for (int c = tid; c < CB; c += TH) {
            int k = c / (BN >> 2), nc = (c % (BN >> 2)) << 2;
            cpa16(&Bs[0][k * BN + nc], W + (size_t)k * N + n0 + nc);
        }
        cpa_commit();
    }

    for (int t = 0; t < nt; t++) {
        cpa_wait0();
        __syncthreads();
        if (t + 1 < nt) {
            int k0 = (t + 1) * BK;
            int nb = (t + 1) & 1;
#pragma unroll
            for (int c = tid; c < CA; c += TH) {
                int r = c >> 2, kc = (c & 3) << 2;
                if (m0 + r < M) cpa16(&As[nb][r * BK + kc], A + (size_t)(m0 + r) * K + k0 + kc);
            }
#pragma unroll
            for (int c = tid; c < CB; c += TH) {
                int k = c / (BN >> 2), nc = (c % (BN >> 2)) << 2;
                cpa16(&Bs[nb][k * BN + nc], W + (size_t)(k0 + k) * N + n0 + nc);
            }
            cpa_commit();
        }
        int b = t & 1;
#pragma unroll
        for (int kk = 0; kk < BK; kk++) {
            float ra[TM], rb[TN];
#pragma unroll
            for (int i = 0; i < TM; i++) ra[i] = As[b][(ty * TM + i) * BK + kk];
            if (TN == 8) {
                float4 b0 = *(float4*)&Bs[b][kk * BN + tx * 8];
                float4 b1 = *(float4*)&Bs[b][kk * BN + tx * 8 + 4];
                rb[0] = b0.x; rb[1] = b0.y; rb[2] = b0.z; rb[3] = b0.w;
                rb[4] = b1.x; rb[5] = b1.y; rb[6] = b1.z; rb[7] = b1.w;
            } else {
#pragma unroll
                for (int j = 0; j < TN; j++) rb[j] = Bs[b][kk * BN + tx * TN + j];
            }
#pragma unroll
            for (int i = 0; i < TM; i++)
#pragma unroll
                for (int j = 0; j < TN; j++) acc[i][j] += ra[i] * rb[j];
        }
        __syncthreads();
    }

#pragma unroll
    for (int i = 0; i < TM; i++) {
        int gm = m0 + ty * TM + i;
        if (gm >= M) continue;
#pragma unroll
        for (int j = 0; j < TN; j++) {
            int gn = n0 + tx * TN + j;
            float v = acc[i][j];
            if (bias) v += bias[gn];
            C[(size_t)gm * N + gn] = v;
        }
    }
}

// big GEMMs (N multiple of 128): BM=128, BN=128, TM=8, TN=8, 256 threads
__global__ void k_g_q1(const float* __restrict__ x, const float* __restrict__ W, const float* __restrict__ b) {
    pgemm<128, 128, 8, 8>(x, W, b, g_q1, NN, INCH, HIDD);
}
__global__ void k_g_k1(const float* __restrict__ x, const float* __restrict__ W, const float* __restrict__ b) {
    pgemm<128, 128, 8, 8>(x, W, b, g_k1, NN, INCH, HIDD);
}
__global__ void k_g_v1(const float* __restrict__ x, const float* __restrict__ W, const float* __restrict__ b) {
    pgemm<128, 128, 8, 8>(x, W, b, g_v1, NN, INCH, HIDD);
}
__global__ void k_g_s1(const float* __restrict__ x, const float* __restrict__ W, const float* __restrict__ b) {
    pgemm<128, 128, 8, 8>(x, W, b, g_s1, NN, INCH, HIDD);
}
__global__ void k_g_e1(const float* __restrict__ W) {
    pgemm<128, 128, 8, 8>(g_edge_attr, W, nullptr, g_e1, EE, EDD, HIDD);
}
// narrow GEMMs (N=32): BM=128, BN=32, TM=8, TN=2, 256 threads
__global__ void k_g_q2(const float* __restrict__ W, const float* __restrict__ b) {
    pgemm<128, 32, 8, 2>(g_h, W, b, g_q2, NN, HIDD, CCH);
}
__global__ void k_g_k2(const float* __restrict__ W, const float* __restrict__ b) {
    pgemm<128, 32, 8, 2>(g_h, W, b, g_k2, NN, HIDD, CCH);
}
__global__ void k_g_v2(const float* __restrict__ W, const float* __restrict__ b) {
    pgemm<128, 32, 8, 2>(g_h, W, b, g_v2, NN, HIDD, CCH);
}
__global__ void k_g_s2(const float* __restrict__ W, const float* __restrict__ b) {
    pgemm<128, 32, 8, 2>(g_h, W, b, g_s2, NN, HIDD, CCH);
}
__global__ void k_g_e2(const float* __restrict__ W) {
    pgemm<128, 32, 8, 2>(g_edge_attr, W, nullptr, g_e2, EE, EDD, CCH);
}

// ---------------- fused attention (CSR, online softmax, + skip + relu) --------
// one warp per (dst, head); lane = channel (C == 32)
template <int H, int C>
__device__ __forceinline__ void attn_body(const float* __restrict__ q,
                                          const float* __restrict__ k,
                                          const float* __restrict__ v,
                                          const float* __restrict__ ev,
                                          const float* __restrict__ skip,
                                          float* __restrict__ outp) {
    int w = (blockIdx.x * blockDim.x + threadIdx.x) >> 5;
    int lane = threadIdx.x & 31;
    if (w >= NN * H) return;
    int d = w / H;
    int h = w - d * H;

    float qc = q[(d * H + h) * C + lane];
    int beg = g_off[d], end = g_off[d + 1];

    float m = -FLT_MAX, ssum = 0.f, acc = 0.f;
    for (int i = beg; i < end; i++) {
        int e = g_eidx[i];
        int s = g_src[e];
        int ebase = (e * H + h) * C + lane;
        int sbase = (s * H + h) * C + lane;
        float ec = ev[ebase];
        float kc = k[sbase] + ec;
        float p = qc * kc;
#pragma unroll
        for (int o = 16; o; o >>= 1) p += __shfl_xor_sync(0xffffffffu, p, o);
        float lg = p * 0.17677669529663687f;  // 1/sqrt(32)
        if (lg > m) {
            float f = expf(m - lg);  // m == -FLT_MAX -> 0
            ssum *= f;
            acc *= f;
            m = lg;
        }
        float wt = expf(lg - m);
        ssum += wt;
        acc += wt * (v[sbase] + ec);
    }
    float val = acc / (ssum + 1e-16f);
    int oi = (d * H + h) * C + lane;
    outp[oi] = fmaxf(val + skip[oi], 0.f);
}
__global__ void k_attn1() { attn_body<HH1, CCH>(g_q1, g_k1, g_v1, g_e1, g_s1, g_h); }
__global__ void k_attn2(float* __restrict__ out) {
    attn_body<1, CCH>(g_q2, g_k2, g_v2, g_e2, g_s2, out);
}

// ---------------- launch ------------------------------------------------------
extern "C" void kernel_launch(void* const* d_in, const int* in_sizes, int n_in,
                              void* d_out, int out_size) {
    const float* x           = (const float*)d_in[0];
    const float* last_update = (const float*)d_in[1];
    const void*  ei          = d_in[2];
    const float* t           = (const float*)d_in[3];
    const float* msg         = (const float*)d_in[4];
    const float* tw          = (const float*)d_in[5];
    const float* tb          = (const float*)d_in[6];
    const float* Wq1 = (const float*)d_in[7],  *bq1 = (const float*)d_in[8];
    const float* Wk1 = (const float*)d_in[9],  *bk1 = (const float*)d_in[10];
    const float* Wv1 = (const float*)d_in[11], *bv1 = (const float*)d_in[12];
    const float* We1 = (const float*)d_in[13];
    const float* Ws1 = (const float*)d_in[14], *bs1 = (const float*)d_in[15];
    const float* Wq2 = (const float*)d_in[16], *bq2 = (const float*)d_in[17];
    const float* Wk2 = (const float*)d_in[18], *bk2 = (const float*)d_in[19];
    const float* Wv2 = (const float*)d_in[20], *bv2 = (const float*)d_in[21];
    const float* We2 = (const float*)d_in[22];
    const float* Ws2 = (const float*)d_in[23], *bs2 = (const float*)d_in[24];

    float* out = (float*)d_out;

    // index ingestion + CSR
    k_detect<<<1, 256>>>((const int*)ei);
    k_convert<<<(EE + 255) / 256, 256>>>(ei);
    k_zero_deg<<<(NN + 255) / 256, 256>>>();
    k_count<<<(EE + 255) / 256, 256>>>();
    k_scan<<<1, 1024>>>();
    k_fill<<<(EE + 255) / 256, 256>>>();

    // edge features
    k_edge_attr<<<(EE * 32 + 255) / 256, 256>>>(last_update, t, msg, tw, tb);

    // layer-1 GEMMs
    {
        dim3 gn(HIDD / 128, (NN + 127) / 128);
        k_g_q1<<<gn, 256>>>(x, Wq1, bq1);
        k_g_k1<<<gn, 256>>>(x, Wk1, bk1);
        k_g_v1<<<gn, 256>>>(x, Wv1, bv1);
        k_g_s1<<<gn, 256>>>(x, Ws1, bs1);
        dim3 ge(HIDD / 128, EE / 128);
        k_g_e1<<<ge, 256>>>(We1);
    }

    // layer-1 fused attention -> g_h (with skip + relu)
    k_attn1<<<(NN * HH1 * 32 + 255) / 256, 256>>>();

    // layer-2 GEMMs (N=32)
    {
        dim3 gn(1, (NN + 127) / 128);
        k_g_q2<<<gn, 256>>>(Wq2, bq2);
        k_g_k2<<<gn, 256>>>(Wk2, bk2);
        k_g_v2<<<gn, 256>>>(Wv2, bv2);
        k_g_s2<<<gn, 256>>>(Ws2, bs2);
        dim3 ge(1, (EE + 127) / 128);
        k_g_e2<<<ge, 256>>>(We2);
    }

    // layer-2 fused attention -> out (with skip + relu)
    k_attn2<<<(NN * 32 + 255) / 256, 256>>>(out);
}